// round 10
// baseline (speedup 1.0000x reference)
#include <cuda_runtime.h>
#include <math_constants.h>

// ProbabilisticChamferDistanceLoss — dot-product form (s = |q|^2 - 2 p.q),
// packed f32x2 FFMA, group-of-8 tree-min + deferred exact argmin (os),
// order-preserving packed atomicMax accumulation across splits,
// slim counter-folded deterministic reduce.

#define N_ORIG 30000
#define M_SIMP 10000

#define JTILE  2000           // Ps tile (os part), divisible by 8
#define JSPLIT 5
#define JPAIRS (JTILE / 2)    // 1000
#define JGROUPS8 (JTILE / 8)  // 250
#define OSX    ((N_ORIG + 511) / 512)      // 59
#define OS_BLOCKS (OSX * JSPLIT)           // 295

#define ITILE  3000           // P tile (so part)
#define ISPLIT 10
#define IPAIRS (ITILE / 2)    // 1500
#define IGROUPS (ITILE / 4)   // 750
#define SOX    ((M_SIMP + 511) / 512)      // 20
#define SO_BLOCKS (SOX * ISPLIT)           // 200

#define TOTAL_BLOCKS (OS_BLOCKS + SO_BLOCKS)   // 495

typedef unsigned long long ull;

// ---- packed f32x2 helpers (sm_103a) ----
__device__ __forceinline__ ull f2_fma(ull a, ull b, ull c) {
    ull r; asm("fma.rn.f32x2 %0, %1, %2, %3;" : "=l"(r) : "l"(a), "l"(b), "l"(c)); return r;
}
__device__ __forceinline__ ull f2_bcast(float v) {
    ull r; unsigned u = __float_as_uint(v);
    asm("mov.b64 %0, {%1, %1};" : "=l"(r) : "r"(u)); return r;
}
__device__ __forceinline__ ull f2_pack(float a, float b) {
    ull r; unsigned ua = __float_as_uint(a), ub = __float_as_uint(b);
    asm("mov.b64 %0, {%1, %2};" : "=l"(r) : "r"(ua), "r"(ub)); return r;
}
__device__ __forceinline__ void f2_unpack(float& lo, float& hi, ull v) {
    unsigned a, b;
    asm("mov.b64 {%0, %1}, %2;" : "=r"(a), "=r"(b) : "l"(v));
    lo = __uint_as_float(a); hi = __uint_as_float(b);
}

// Scratch (device globals, zero-initialized at load; reduce resets to 0 each replay)
// os key: (~bits(d2) << 32) | ~j   — atomicMax => min d2, tie => min j (first occurrence)
// so key: ~bits(d2)                — atomicMax => min d2
__device__ ull      g_os_key[N_ORIG];
__device__ unsigned g_so_key[M_SIMP];
__device__ float    g_part[384];
__device__ int      g_count;

__device__ __forceinline__ ull make_os_key(float d2, int j) {
    return ((ull)(~__float_as_uint(d2)) << 32) | (ull)(unsigned)(~j);
}

// 8 distances (4 packed pairs) of group g vs one query.
__device__ __forceinline__ void group8_dists(const float4* __restrict__ sxy,
                                             const float4* __restrict__ szc,
                                             int g, ull mx, ull my, ull mz,
                                             float* v /*[8]*/) {
#pragma unroll
    for (int p = 0; p < 4; ++p) {
        const float4 a = sxy[4 * g + p];
        const float4 zc = szc[4 * g + p];
        const ull x01 = f2_pack(a.x, a.y);
        const ull y01 = f2_pack(a.z, a.w);
        const ull z01 = f2_pack(zc.x, zc.y);
        const ull c01 = f2_pack(zc.z, zc.w);
        ull t = f2_fma(mz, z01, c01);
        t = f2_fma(my, y01, t);
        t = f2_fma(mx, x01, t);
        f2_unpack(v[2 * p], v[2 * p + 1], t);
    }
}

// ---------------------------------------------------------------------------
// Fused main kernel: blocks [0, OS_BLOCKS) do o->s (min+argmin), rest s->o.
// Tile: sxy[k]=(x0,x1,y0,y1)  szc[k]=(z0,z1,c0,c1), c=|pt|^2, pair-interleaved.
// ---------------------------------------------------------------------------
__global__ __launch_bounds__(256) void kern_main(const float* __restrict__ P,
                                                 const float* __restrict__ Ps) {
    __shared__ float4 sxy[IPAIRS];   // sized for the larger (so) tile
    __shared__ float4 szc[IPAIRS];

    const int tid = threadIdx.x;
    const int b = blockIdx.x;

    if (b < OS_BLOCKS) {
        // ---------------- o -> s ----------------
        const int bx = b % OSX;
        const int by = b / OSX;
        const int jbase = by * JTILE;

        for (int k = tid; k < JPAIRS; k += 256) {
            const int j0 = jbase + 2 * k;
            const float x0 = Ps[3 * j0],     y0 = Ps[3 * j0 + 1], z0 = Ps[3 * j0 + 2];
            const float x1 = Ps[3 * j0 + 3], y1 = Ps[3 * j0 + 4], z1 = Ps[3 * j0 + 5];
            sxy[k] = make_float4(x0, x1, y0, y1);
            const float c0 = fmaf(x0, x0, fmaf(y0, y0, z0 * z0));
            const float c1 = fmaf(x1, x1, fmaf(y1, y1, z1 * z1));
            szc[k] = make_float4(z0, z1, c0, c1);
        }
        __syncthreads();

        const int i0 = bx * 512 + tid;
        const int i1 = i0 + 256;
        const bool v0 = (i0 < N_ORIG), v1 = (i1 < N_ORIG);
        const int r0 = v0 ? i0 : 0, r1 = v1 ? i1 : 0;

        const float p0x = P[3 * r0], p0y = P[3 * r0 + 1], p0z = P[3 * r0 + 2];
        const float p1x = P[3 * r1], p1y = P[3 * r1 + 1], p1z = P[3 * r1 + 2];
        const ull m0x = f2_bcast(-2.0f * p0x), m0y = f2_bcast(-2.0f * p0y), m0z = f2_bcast(-2.0f * p0z);
        const ull m1x = f2_bcast(-2.0f * p1x), m1y = f2_bcast(-2.0f * p1y), m1z = f2_bcast(-2.0f * p1z);
        const float p0sq = fmaf(p0x, p0x, fmaf(p0y, p0y, p0z * p0z));
        const float p1sq = fmaf(p1x, p1x, fmaf(p1y, p1y, p1z * p1z));

        float best0 = CUDART_INF_F, best1 = CUDART_INF_F;
        int bg0 = 0, bg1 = 0;

#pragma unroll 2
        for (int g = 0; g < JGROUPS8; ++g) {
            {
                float v[8];
                group8_dists(sxy, szc, g, m0x, m0y, m0z, v);
                const float m = fminf(fminf(fminf(v[0], v[1]), fminf(v[2], v[3])),
                                      fminf(fminf(v[4], v[5]), fminf(v[6], v[7])));
                if (m < best0) { best0 = m; bg0 = g; }   // strict < => earliest group
            }
            {
                float v[8];
                group8_dists(sxy, szc, g, m1x, m1y, m1z, v);
                const float m = fminf(fminf(fminf(v[0], v[1]), fminf(v[2], v[3])),
                                      fminf(fminf(v[4], v[5]), fminf(v[6], v[7])));
                if (m < best1) { best1 = m; bg1 = g; }
            }
        }

        // Deferred exact argmin: recompute winning group (bitwise identical),
        // first-occurrence tie-break within the group.
        if (v0) {
            float v[8];
            group8_dists(sxy, szc, bg0, m0x, m0y, m0z, v);
            int off = 7;
#pragma unroll
            for (int t = 6; t >= 0; --t)
                if (v[t] == best0) off = t;      // last-executed lowest t wins
            const float d2 = fmaxf(best0 + p0sq, 0.0f);
            atomicMax(&g_os_key[i0], make_os_key(d2, jbase + 8 * bg0 + off));
        }
        if (v1) {
            float v[8];
            group8_dists(sxy, szc, bg1, m1x, m1y, m1z, v);
            int off = 7;
#pragma unroll
            for (int t = 6; t >= 0; --t)
                if (v[t] == best1) off = t;
            const float d2 = fmaxf(best1 + p1sq, 0.0f);
            atomicMax(&g_os_key[i1], make_os_key(d2, jbase + 8 * bg1 + off));
        }
    } else {
        // ---------------- s -> o ----------------
        const int bb = b - OS_BLOCKS;
        const int bx = bb % SOX;
        const int by = bb / SOX;
        const int ibase = by * ITILE;

        for (int k = tid; k < IPAIRS; k += 256) {
            const int i0 = ibase + 2 * k;
            const float x0 = P[3 * i0],     y0 = P[3 * i0 + 1], z0 = P[3 * i0 + 2];
            const float x1 = P[3 * i0 + 3], y1 = P[3 * i0 + 4], z1 = P[3 * i0 + 5];
            sxy[k] = make_float4(x0, x1, y0, y1);
            const float c0 = fmaf(x0, x0, fmaf(y0, y0, z0 * z0));
            const float c1 = fmaf(x1, x1, fmaf(y1, y1, z1 * z1));
            szc[k] = make_float4(z0, z1, c0, c1);
        }
        __syncthreads();

        const int j0 = bx * 512 + tid;
        const int j1 = j0 + 256;
        const bool v0 = (j0 < M_SIMP), v1 = (j1 < M_SIMP);
        const int r0 = v0 ? j0 : 0, r1 = v1 ? j1 : 0;

        const float q0x = Ps[3 * r0], q0y = Ps[3 * r0 + 1], q0z = Ps[3 * r0 + 2];
        const float q1x = Ps[3 * r1], q1y = Ps[3 * r1 + 1], q1z = Ps[3 * r1 + 2];
        const ull m0x = f2_bcast(-2.0f * q0x), m0y = f2_bcast(-2.0f * q0y), m0z = f2_bcast(-2.0f * q0z);
        const ull m1x = f2_bcast(-2.0f * q1x), m1y = f2_bcast(-2.0f * q1y), m1z = f2_bcast(-2.0f * q1z);
        const float q0sq = fmaf(q0x, q0x, fmaf(q0y, q0y, q0z * q0z));
        const float q1sq = fmaf(q1x, q1x, fmaf(q1y, q1y, q1z * q1z));

        float best0 = CUDART_INF_F, best1 = CUDART_INF_F;

#pragma unroll 4
        for (int g = 0; g < IGROUPS; ++g) {
            const float4 aA = sxy[2 * g],     zA = szc[2 * g];
            const float4 aB = sxy[2 * g + 1], zB = szc[2 * g + 1];
            const ull x01A = f2_pack(aA.x, aA.y), y01A = f2_pack(aA.z, aA.w);
            const ull z01A = f2_pack(zA.x, zA.y), c01A = f2_pack(zA.z, zA.w);
            const ull x01B = f2_pack(aB.x, aB.y), y01B = f2_pack(aB.z, aB.w);
            const ull z01B = f2_pack(zB.x, zB.y), c01B = f2_pack(zB.z, zB.w);
            {
                ull tA = f2_fma(m0z, z01A, c01A); tA = f2_fma(m0y, y01A, tA); tA = f2_fma(m0x, x01A, tA);
                ull tB = f2_fma(m0z, z01B, c01B); tB = f2_fma(m0y, y01B, tB); tB = f2_fma(m0x, x01B, tB);
                float a0, a1, b0, b1;
                f2_unpack(a0, a1, tA); f2_unpack(b0, b1, tB);
                best0 = fminf(best0, fminf(fminf(a0, a1), fminf(b0, b1)));
            }
            {
                ull tA = f2_fma(m1z, z01A, c01A); tA = f2_fma(m1y, y01A, tA); tA = f2_fma(m1x, x01A, tA);
                ull tB = f2_fma(m1z, z01B, c01B); tB = f2_fma(m1y, y01B, tB); tB = f2_fma(m1x, x01B, tB);
                float a0, a1, b0, b1;
                f2_unpack(a0, a1, tA); f2_unpack(b0, b1, tB);
                best1 = fminf(best1, fminf(fminf(a0, a1), fminf(b0, b1)));
            }
        }

        if (v0) atomicMax(&g_so_key[j0], ~__float_as_uint(fmaxf(best0 + q0sq, 0.0f)));
        if (v1) atomicMax(&g_so_key[j1], ~__float_as_uint(fmaxf(best1 + q1sq, 0.0f)));
    }
}

// ---------------------------------------------------------------------------
// Reduce: one key per point (no split loop), sqrt + prob weight, shuffle sums;
// counter-elected last block does fixed-order final sum; resets keys for next
// graph replay.
// ---------------------------------------------------------------------------
#define RT 128
#define RB ((N_ORIG + M_SIMP + RT - 1) / RT)   // 313

__global__ __launch_bounds__(RT) void kern_reduce(const float* __restrict__ prob,
                                                  float* __restrict__ out) {
    const int idx = blockIdx.x * RT + threadIdx.x;

    float local = 0.0f;
    if (idx < N_ORIG) {
        const ull key = g_os_key[idx];
        const float d2 = __uint_as_float(~(unsigned)(key >> 32));
        const int bj = (int)(~(unsigned)(key & 0xffffffffull));
        local = sqrtf(d2) * prob[bj];
        g_os_key[idx] = 0;                    // reset for next replay
    } else if (idx < N_ORIG + M_SIMP) {
        const int j = idx - N_ORIG;
        const float d2 = __uint_as_float(~g_so_key[j]);
        local = sqrtf(d2) * prob[j];
        g_so_key[j] = 0;                      // reset for next replay
    }

    // intra-warp fixed-order reduction
#pragma unroll
    for (int off = 16; off > 0; off >>= 1)
        local += __shfl_down_sync(0xFFFFFFFFu, local, off);

    __shared__ float warpsum[RT / 32];
    if ((threadIdx.x & 31) == 0) warpsum[threadIdx.x >> 5] = local;
    __syncthreads();

    __shared__ bool amLast;
    if (threadIdx.x == 0) {
        float s = 0.0f;
#pragma unroll
        for (int w = 0; w < RT / 32; ++w) s += warpsum[w];
        g_part[blockIdx.x] = s;
        __threadfence();
        amLast = (atomicAdd(&g_count, 1) == gridDim.x - 1);
    }
    __syncthreads();

    if (amLast) {
        // fixed-order final sum over RB partials (deterministic)
        float s = 0.0f;
#pragma unroll
        for (int base = 0; base < RB; base += RT) {
            const int p = base + threadIdx.x;
            if (p < RB) s += __ldcg(&g_part[p]);
        }
#pragma unroll
        for (int off = 16; off > 0; off >>= 1)
            s += __shfl_down_sync(0xFFFFFFFFu, s, off);
        if ((threadIdx.x & 31) == 0) warpsum[threadIdx.x >> 5] = s;
        __syncthreads();
        if (threadIdx.x == 0) {
            float t = 0.0f;
#pragma unroll
            for (int w = 0; w < RT / 32; ++w) t += warpsum[w];
            out[0] = t;
            g_count = 0;     // reset for next graph replay
        }
    }
}

extern "C" void kernel_launch(void* const* d_in, const int* in_sizes, int n_in,
                              void* d_out, int out_size) {
    const float* P    = (const float*)d_in[0];   // (N, 3)
    const float* Ps   = (const float*)d_in[1];   // (M, 3)
    const float* prob = (const float*)d_in[2];   // (M,)
    float* out = (float*)d_out;

    kern_main<<<TOTAL_BLOCKS, 256>>>(P, Ps);
    kern_reduce<<<RB, RT>>>(prob, out);
}